// round 4
// baseline (speedup 1.0000x reference)
#include <cuda_runtime.h>
#include <cuda_bf16.h>
#include <cstdint>
#include <math.h>

// ---------------- problem constants ----------------
#define BATCH      16
#define IMG_H      60
#define IMG_W      60
#define F1         256
#define F2         256
#define CONV1_H    52
#define CONV1_W    52
#define NPOS       484
#define CAP_DIM    8
#define NUM_MAP    32
#define PP         15488
#define NCLASS     10
#define DDIM       16
#define KTOT       20736        // 256*81
#define NTOT       7744         // 16*484
#define H1N        512
#define H2N        1024
#define RECN       3600

#define OUT_Y_OFF    0
#define OUT_REC_OFF  160
#define OUT_VL_OFF   57760

// ---------------- scratch ----------------
__device__ unsigned       g_x1p[BATCH * F1 * CONV1_H * CONV1_W]; // packed bf16 hi|lo<<16
__device__ unsigned short g_wh [F2 * KTOT];                      // W hi plane
__device__ unsigned short g_wl [F2 * KTOT];                      // W lo plane
__device__ int      g_koff[KTOT];
__device__ float g_pc[BATCH * F2 * NPOS];
__device__ float g_u [BATCH * PP * CAP_DIM];
__device__ float g_bij[BATCH * NCLASS * PP];
__device__ float g_v [BATCH * NCLASS * DDIM];
__device__ float g_wv[BATCH * NCLASS * CAP_DIM];
__device__ float g_m [BATCH * NCLASS * DDIM];
__device__ float g_h1[BATCH * H1N];
__device__ float g_h2[BATCH * H2N];

__device__ __forceinline__ unsigned pack_bf16x2(float v) {
    __nv_bfloat16 h = __float2bfloat16(v);
    float hf = __bfloat162float(h);
    __nv_bfloat16 l = __float2bfloat16(v - hf);
    return (unsigned)__bfloat16_as_ushort(h) | ((unsigned)__bfloat16_as_ushort(l) << 16);
}

__device__ __forceinline__ uint32_t smem_u32(const void* p) {
    uint32_t a;
    asm("{ .reg .u64 t; cvta.to.shared.u64 t, %1; cvt.u32.u64 %0, t; }" : "=r"(a) : "l"(p));
    return a;
}
__device__ __forceinline__ void cpasync16(uint32_t dst, const void* src) {
    asm volatile("cp.async.ca.shared.global [%0], [%1], 16;" :: "r"(dst), "l"(src));
}
__device__ __forceinline__ void cp_commit() {
    asm volatile("cp.async.commit_group;" ::: "memory");
}
template<int N>
__device__ __forceinline__ void cp_wait() {
    asm volatile("cp.async.wait_group %0;" :: "n"(N) : "memory");
}
__device__ __forceinline__ void ldmx4(uint32_t* r, uint32_t addr) {
    asm volatile("ldmatrix.sync.aligned.m8n8.x4.shared.b16 {%0,%1,%2,%3}, [%4];"
                 : "=r"(r[0]), "=r"(r[1]), "=r"(r[2]), "=r"(r[3]) : "r"(addr));
}
__device__ __forceinline__ void mma16816(float* c, const uint32_t* a, const uint32_t* b) {
    asm volatile(
        "mma.sync.aligned.m16n8k16.row.col.f32.bf16.bf16.f32 "
        "{%0,%1,%2,%3}, {%4,%5,%6,%7}, {%8,%9}, {%0,%1,%2,%3};"
        : "+f"(c[0]), "+f"(c[1]), "+f"(c[2]), "+f"(c[3])
        : "r"(a[0]), "r"(a[1]), "r"(a[2]), "r"(a[3]), "r"(b[0]), "r"(b[1]));
}

// ---------------- conv1 + relu -> packed bf16 hi/lo ----------------
__global__ __launch_bounds__(256) void conv1_kernel(
    const float* __restrict__ img, const float* __restrict__ w,
    const float* __restrict__ bias)
{
    const int ocg = blockIdx.x, oy = blockIdx.y, b = blockIdx.z;
    __shared__ float xs[9][60];
    __shared__ float ws[64 * 81];
    const int tid = threadIdx.x;

    for (int idx = tid; idx < 540; idx += 256) {
        int r = idx / 60, col = idx - r * 60;
        xs[r][col] = img[b * 3600 + (oy + r) * 60 + col];
    }
    for (int idx = tid; idx < 5184; idx += 256)
        ws[idx] = w[ocg * 5184 + idx];
    __syncthreads();

    const int o = tid >> 2;
    const int q = tid & 3;
    float acc[13];
#pragma unroll
    for (int r = 0; r < 13; r++) acc[r] = 0.f;
#pragma unroll
    for (int ky = 0; ky < 9; ky++) {
#pragma unroll
        for (int kx = 0; kx < 9; kx++) {
            float wv = ws[o * 81 + ky * 9 + kx];
#pragma unroll
            for (int r = 0; r < 13; r++)
                acc[r] += wv * xs[ky][q + 4 * r + kx];
        }
    }
    const int oc = ocg * 64 + o;
    const float bia = bias[oc];
    const int base = ((b * F1 + oc) * CONV1_H + oy) * CONV1_W;
#pragma unroll
    for (int r = 0; r < 13; r++)
        g_x1p[base + q + 4 * r] = pack_bf16x2(fmaxf(acc[r] + bia, 0.f));
}

// ---------------- W split + koff table ----------------
__global__ __launch_bounds__(256) void wprep_kernel(const float* __restrict__ w)
{
    int i = blockIdx.x * 256 + threadIdx.x;
    if (i < F2 * KTOT) {
        float v = w[i];
        __nv_bfloat16 h = __float2bfloat16(v);
        float hf = __bfloat162float(h);
        __nv_bfloat16 l = __float2bfloat16(v - hf);
        g_wh[i] = __bfloat16_as_ushort(h);
        g_wl[i] = __bfloat16_as_ushort(l);
    }
    if (i < KTOT) {
        int ci = i / 81, r = i - ci * 81;
        int ky = r / 9, kx = r - ky * 9;
        g_koff[i] = ci * (CONV1_H * CONV1_W) + ky * CONV1_W + kx;
    }
}

// ---------------- pconv: mma.sync bf16 3-pass implicit GEMM ----------------
#define BK        32
#define NST       3
#define A_STRIDE  80
#define A_BYTES   (256 * A_STRIDE)
#define B_BYTES   (64 * A_STRIDE)
#define STG       (2 * A_BYTES + 2 * B_BYTES)   // 51200
#define NCHUNK    (KTOT / BK)                   // 648

__global__ __launch_bounds__(256, 1) void pconv_mma_kernel(const float* __restrict__ bias)
{
    extern __shared__ __align__(128) char smem[];
    const uint32_t sb = smem_u32(smem);
    const int tid = threadIdx.x;
    const int lane = tid & 31;
    const int warp = tid >> 5;
    const int wm = warp & 3;
    const int wn = warp >> 2;
    const int pos0 = blockIdx.x * 64;

    const int brow = tid & 63;
    const int bkq  = tid >> 6;
    int nb;
    {
        int n = pos0 + brow;
        int bb = n / NPOS, pos = n - bb * NPOS;
        int oy = pos / 22, ox = pos - oy * 22;
        nb = bb * (F1 * CONV1_H * CONV1_W) + oy * (2 * CONV1_W) + ox * 2;
    }

    float acc[4][4][4];
#pragma unroll
    for (int i = 0; i < 4; i++)
#pragma unroll
        for (int j = 0; j < 4; j++)
#pragma unroll
            for (int q = 0; q < 4; q++) acc[i][j][q] = 0.f;

    // A loader (cp.async) for chunk i into stage s
    auto load_A = [&](int s, int i) {
        const int kc = i * BK;
        const unsigned short* srcH = g_wh + (size_t)tid * KTOT + kc;
        const unsigned short* srcL = g_wl + (size_t)tid * KTOT + kc;
        uint32_t dh = sb + s * STG + tid * A_STRIDE;
        uint32_t dl = dh + A_BYTES;
#pragma unroll
        for (int q = 0; q < 4; q++) {
            cpasync16(dh + q * 16, srcH + q * 8);
            cpasync16(dl + q * 16, srcL + q * 8);
        }
    };
    // B gather into regs
    auto gather_B = [&](int i, unsigned* p) {
        const int* ko = g_koff + i * BK + bkq * 8;
        int4 k0 = ((const int4*)ko)[0];
        int4 k1 = ((const int4*)ko)[1];
        p[0] = __ldg(&g_x1p[nb + k0.x]);
        p[1] = __ldg(&g_x1p[nb + k0.y]);
        p[2] = __ldg(&g_x1p[nb + k0.z]);
        p[3] = __ldg(&g_x1p[nb + k0.w]);
        p[4] = __ldg(&g_x1p[nb + k1.x]);
        p[5] = __ldg(&g_x1p[nb + k1.y]);
        p[6] = __ldg(&g_x1p[nb + k1.z]);
        p[7] = __ldg(&g_x1p[nb + k1.w]);
    };
    // B split + STS for chunk i into stage s
    auto store_B = [&](int s, const unsigned* p) {
        uint4 hi = make_uint4(__byte_perm(p[0], p[1], 0x5410), __byte_perm(p[2], p[3], 0x5410),
                              __byte_perm(p[4], p[5], 0x5410), __byte_perm(p[6], p[7], 0x5410));
        uint4 lo = make_uint4(__byte_perm(p[0], p[1], 0x7632), __byte_perm(p[2], p[3], 0x7632),
                              __byte_perm(p[4], p[5], 0x7632), __byte_perm(p[6], p[7], 0x7632));
        uint32_t db = s * STG + 2 * A_BYTES + brow * A_STRIDE + bkq * 16;
        *(uint4*)(smem + db) = hi;
        *(uint4*)(smem + db + B_BYTES) = lo;
    };

    // prologue: fill stages 0..NST-2 completely
#pragma unroll
    for (int s = 0; s < NST - 1; s++) {
        unsigned pr[8];
        gather_B(s, pr);
        load_A(s, s);
        store_B(s, pr);
        cp_commit();
    }

    const uint32_t a_row = (uint32_t)(wm * 64 + (lane & 15));
    const uint32_t a_koff = (uint32_t)((lane >> 4) * 16);
    const uint32_t b_row_base = (uint32_t)(wn * 32 + ((lane >> 4) & 1) * 8 + (lane & 7));
    const uint32_t b_koff = (uint32_t)(((lane >> 3) & 1) * 16);

    for (int i = 0; i < NCHUNK; i++) {
        cp_wait<NST - 2>();
        __syncthreads();

        // prefetch B loads for chunk i+NST-1 (stage free after the sync above)
        const int nx = i + NST - 1;
        unsigned pr[8];
        if (nx < NCHUNK) {
            gather_B(nx, pr);
            load_A(nx % NST, nx);
        }

        const int s = i % NST;
        const uint32_t ah_base = sb + s * STG;
        const uint32_t al_base = ah_base + A_BYTES;
        const uint32_t bh_base = ah_base + 2 * A_BYTES;
        const uint32_t bl_base = bh_base + B_BYTES;

#pragma unroll
        for (int kk = 0; kk < 2; kk++) {
            uint32_t a_h[4][4], a_l[4][4], b_h[2][4], b_l[2][4];
#pragma unroll
            for (int mt = 0; mt < 4; mt++) {
                uint32_t off = (a_row + mt * 16) * A_STRIDE + kk * 32 + a_koff;
                ldmx4(a_h[mt], ah_base + off);
                ldmx4(a_l[mt], al_base + off);
            }
#pragma unroll
            for (int nt2 = 0; nt2 < 2; nt2++) {
                uint32_t off = (b_row_base + nt2 * 16) * A_STRIDE + kk * 32 + b_koff;
                ldmx4(b_h[nt2], bh_base + off);
                ldmx4(b_l[nt2], bl_base + off);
            }
            // pass-major: no back-to-back RAW on any acc
#pragma unroll
            for (int mt = 0; mt < 4; mt++)
#pragma unroll
                for (int nt = 0; nt < 4; nt++)
                    mma16816(acc[mt][nt], a_h[mt], &b_h[nt >> 1][(nt & 1) * 2]);
#pragma unroll
            for (int mt = 0; mt < 4; mt++)
#pragma unroll
                for (int nt = 0; nt < 4; nt++)
                    mma16816(acc[mt][nt], a_h[mt], &b_l[nt >> 1][(nt & 1) * 2]);
#pragma unroll
            for (int mt = 0; mt < 4; mt++)
#pragma unroll
                for (int nt = 0; nt < 4; nt++)
                    mma16816(acc[mt][nt], a_l[mt], &b_h[nt >> 1][(nt & 1) * 2]);
        }

        if (nx < NCHUNK) store_B(nx % NST, pr);
        cp_commit();
    }

    // ---- epilogue ----
    const int g = lane >> 2, t0 = lane & 3;
#pragma unroll
    for (int mt = 0; mt < 4; mt++) {
        int oc0 = wm * 64 + mt * 16 + g;
        float bia0 = bias[oc0], bia1 = bias[oc0 + 8];
#pragma unroll
        for (int nt = 0; nt < 4; nt++) {
            int n0 = pos0 + wn * 32 + nt * 8 + 2 * t0;
#pragma unroll
            for (int e = 0; e < 2; e++) {
                int n = n0 + e;
                int bb = n / NPOS, pos = n - bb * NPOS;
                size_t base = ((size_t)(bb * F2)) * NPOS + pos;
                g_pc[base + (size_t)oc0 * NPOS] = acc[mt][nt][e] + bia0;
                g_pc[base + (size_t)(oc0 + 8) * NPOS] = acc[mt][nt][2 + e] + bia1;
            }
        }
    }
}

// ---------------- gather channels + squash -> u[b][p][8] ----------------
__global__ __launch_bounds__(256) void usquash_kernel()
{
    int i = blockIdx.x * 256 + threadIdx.x;
    if (i >= BATCH * PP) return;
    int b = i / PP, p = i - b * PP;
    int mm = p / NPOS, pos = p - mm * NPOS;
    float uu[8]; float sq = 0.f;
#pragma unroll
    for (int e = 0; e < 8; e++) {
        uu[e] = g_pc[((size_t)b * F2 + e * NUM_MAP + mm) * NPOS + pos];
        sq += uu[e] * uu[e];
    }
    float sc = (sq / (1.f + sq)) * rsqrtf(sq + 1e-8f);
    float4* up = (float4*)(g_u + (size_t)i * 8);
    up[0] = make_float4(uu[0] * sc, uu[1] * sc, uu[2] * sc, uu[3] * sc);
    up[1] = make_float4(uu[4] * sc, uu[5] * sc, uu[6] * sc, uu[7] * sc);
}

// ---------------- routing (1024 thr, shuffle reductions) ----------------
template<bool FIRST>
__global__ __launch_bounds__(1024) void routing_iter(const float* __restrict__ Wd)
{
    const int bc = blockIdx.x;
    const int b = bc / NCLASS, c = bc - b * NCLASS;
    const int tid = threadIdx.x;
    const int lane = tid & 31, wid = tid >> 5;
    __shared__ float swarp[32][10];
    __shared__ float sres[9];
    __shared__ float sM;
    __shared__ float sv16[16];
    __shared__ float sscale;

    const float* bptr = g_bij + (size_t)bc * PP;
    float M = 0.f;
    if (!FIRST) {
        float ml = -1e30f;
        for (int p = tid; p < PP; p += 1024) ml = fmaxf(ml, bptr[p]);
#pragma unroll
        for (int off = 16; off > 0; off >>= 1)
            ml = fmaxf(ml, __shfl_xor_sync(0xffffffffu, ml, off));
        if (lane == 0) swarp[wid][0] = ml;
        __syncthreads();
        if (tid == 0) {
            float mm = swarp[0][0];
            for (int w2 = 1; w2 < 32; w2++) mm = fmaxf(mm, swarp[w2][0]);
            sM = mm;
        }
        __syncthreads();
        M = sM;
    }

    float vals[9];
#pragma unroll
    for (int r = 0; r < 9; r++) vals[r] = 0.f;
    const float4* up = (const float4*)(g_u + (size_t)b * PP * 8);
    for (int p = tid; p < PP; p += 1024) {
        float wgt = FIRST ? 1.f : __expf(bptr[p] - M);
        float4 u0 = up[p * 2], u1 = up[p * 2 + 1];
        vals[0] += wgt;
        vals[1] += wgt * u0.x; vals[2] += wgt * u0.y;
        vals[3] += wgt * u0.z; vals[4] += wgt * u0.w;
        vals[5] += wgt * u1.x; vals[6] += wgt * u1.y;
        vals[7] += wgt * u1.z; vals[8] += wgt * u1.w;
    }
#pragma unroll
    for (int r = 0; r < 9; r++)
#pragma unroll
        for (int off = 16; off > 0; off >>= 1)
            vals[r] += __shfl_xor_sync(0xffffffffu, vals[r], off);
    if (lane == 0)
#pragma unroll
        for (int r = 0; r < 9; r++) swarp[wid][r] = vals[r];
    __syncthreads();
    if (tid < 9) {
        float s = 0.f;
        for (int w2 = 0; w2 < 32; w2++) s += swarp[w2][tid];
        sres[tid] = s;
    }
    __syncthreads();

    const float Zt = sres[0];
    if (tid < DDIM) {
        float s = 0.f;
#pragma unroll
        for (int e = 0; e < 8; e++)
            s += Wd[(c * DDIM + tid) * 8 + e] * (sres[1 + e] / Zt);
        sv16[tid] = s;
    }
    __syncthreads();
    if (tid == 0) {
        float sq = 0.f;
#pragma unroll
        for (int d = 0; d < DDIM; d++) sq += sv16[d] * sv16[d];
        sscale = (sq / (1.f + sq)) * rsqrtf(sq + 1e-8f);
    }
    __syncthreads();
    if (tid < DDIM) {
        float vd = sv16[tid] * sscale;
        g_v[bc * DDIM + tid] = vd;
        sv16[tid] = vd;
    }
    __syncthreads();
    if (tid < CAP_DIM) {
        float w2 = 0.f;
#pragma unroll
        for (int d = 0; d < DDIM; d++)
            w2 += Wd[(c * DDIM + d) * 8 + tid] * sv16[d];
        g_wv[bc * CAP_DIM + tid] = w2;
    }
}

template<bool INIT>
__global__ __launch_bounds__(256) void routing_update()
{
    int i = blockIdx.x * 256 + threadIdx.x;
    if (i >= BATCH * PP) return;
    int b = i / PP, p = i - b * PP;
    const float4* up = (const float4*)(g_u + (size_t)i * 8);
    float4 u0 = up[0], u1 = up[1];
    const float* wvb = g_wv + b * NCLASS * CAP_DIM;
#pragma unroll
    for (int c = 0; c < NCLASS; c++) {
        const float* wv = wvb + c * 8;
        float d = u0.x * wv[0] + u0.y * wv[1] + u0.z * wv[2] + u0.w * wv[3]
                + u1.x * wv[4] + u1.y * wv[5] + u1.z * wv[6] + u1.w * wv[7];
        float* dst = &g_bij[((size_t)(b * NCLASS + c)) * PP + p];
        if (INIT) *dst = d; else *dst += d;
    }
}

// ---------------- finalize ----------------
__global__ void finalize_kernel(float* __restrict__ out)
{
    const int b = blockIdx.x, tid = threadIdx.x;
    __shared__ float svl[NCLASS];
    __shared__ int spred;
    if (tid < NCLASS) {
        float sq = 0.f;
#pragma unroll
        for (int d = 0; d < DDIM; d++) {
            float vv = g_v[(b * NCLASS + tid) * DDIM + d];
            sq += vv * vv;
        }
        svl[tid] = sqrtf(sq);
    }
    __syncthreads();
    if (tid == 0) {
        int pm = 0; float best = svl[0];
        for (int c = 1; c < NCLASS; c++)
            if (svl[c] > best) { best = svl[c]; pm = c; }
        spred = pm;
    }
    __syncthreads();
    if (tid < NCLASS) {
        out[OUT_Y_OFF + b * NCLASS + tid] = (tid == spred) ? 1.0f : 0.0f;
        out[OUT_VL_OFF + b * NCLASS + tid] = svl[tid];
    }
    for (int idx = tid; idx < NCLASS * DDIM; idx += 32) {
        int c = idx >> 4, d = idx & 15;
        g_m[b * NCLASS * DDIM + idx] =
            (c == spred) ? g_v[(b * NCLASS + c) * DDIM + d] : 0.f;
    }
}

// ---------------- decoder ----------------
__global__ __launch_bounds__(256) void dec1_kernel(
    const float* __restrict__ w, const float* __restrict__ bias)
{
    int g = blockIdx.x * 256 + threadIdx.x;
    int b = g >> 9, j = g & 511;
    float acc = bias[j];
#pragma unroll 8
    for (int i = 0; i < 160; i++)
        acc += g_m[b * 160 + i] * w[i * H1N + j];
    g_h1[g] = fmaxf(acc, 0.f);
}

__global__ __launch_bounds__(256) void dec2_kernel(
    const float* __restrict__ w, const float* __restrict__ bias)
{
    int g = blockIdx.x * 256 + threadIdx.x;
    int b = g >> 10, j = g & 1023;
    float acc = bias[j];
#pragma unroll 8
    for (int i = 0; i < H1N; i++)
        acc += g_h1[b * H1N + i] * w[i * H2N + j];
    g_h2[g] = fmaxf(acc, 0.f);
}

__global__ __launch_bounds__(256) void dec3_kernel(
    const float* __restrict__ w, const float* __restrict__ bias,
    float* __restrict__ out)
{
    int jl = threadIdx.x >> 4, b = threadIdx.x & 15;
    int j = blockIdx.x * 16 + jl;
    float acc = bias[j];
#pragma unroll 8
    for (int i = 0; i < H2N; i++)
        acc += g_h2[b * H2N + i] * w[i * RECN + j];
    out[OUT_REC_OFF + b * RECN + j] = 1.f / (1.f + expf(-acc));
}

// ---------------- launch ----------------
extern "C" void kernel_launch(void* const* d_in, const int* in_sizes, int n_in,
                              void* d_out, int out_size)
{
    const float* imgs    = (const float*)d_in[0];
    const float* conv1_w = (const float*)d_in[1];
    const float* conv1_b = (const float*)d_in[2];
    const float* pconv_w = (const float*)d_in[3];
    const float* pconv_b = (const float*)d_in[4];
    const float* W_digit = (const float*)d_in[5];
    const float* dec_w1  = (const float*)d_in[6];
    const float* dec_b1  = (const float*)d_in[7];
    const float* dec_w2  = (const float*)d_in[8];
    const float* dec_b2  = (const float*)d_in[9];
    const float* dec_w3  = (const float*)d_in[10];
    const float* dec_b3  = (const float*)d_in[11];
    float* out = (float*)d_out;

    const int smem_bytes = NST * STG;   // 153600
    cudaFuncSetAttribute(pconv_mma_kernel,
                         cudaFuncAttributeMaxDynamicSharedMemorySize, smem_bytes);

    conv1_kernel<<<dim3(4, CONV1_H, BATCH), 256>>>(imgs, conv1_w, conv1_b);
    wprep_kernel<<<(F2 * KTOT + 255) / 256, 256>>>(pconv_w);
    pconv_mma_kernel<<<NTOT / 64, 256, smem_bytes>>>(pconv_b);
    usquash_kernel<<<(BATCH * PP) / 256, 256>>>();

    routing_iter<true><<<BATCH * NCLASS, 1024>>>(W_digit);
    routing_update<true><<<(BATCH * PP) / 256, 256>>>();
    routing_iter<false><<<BATCH * NCLASS, 1024>>>(W_digit);
    routing_update<false><<<(BATCH * PP) / 256, 256>>>();
    routing_iter<false><<<BATCH * NCLASS, 1024>>>(W_digit);

    finalize_kernel<<<BATCH, 32>>>(out);
    dec1_kernel<<<(BATCH * H1N) / 256, 256>>>(dec_w1, dec_b1);
    dec2_kernel<<<(BATCH * H2N) / 256, 256>>>(dec_w2, dec_b2);
    dec3_kernel<<<RECN / 16, 256>>>(dec_w3, dec_b3, out);
}

// round 5
// speedup vs baseline: 1.0492x; 1.0492x over previous
#include <cuda_runtime.h>
#include <cuda_bf16.h>
#include <cstdint>
#include <math.h>

// ---------------- problem constants ----------------
#define BATCH      16
#define IMG_H      60
#define IMG_W      60
#define F1         256
#define F2         256
#define CONV1_H    52
#define CONV1_W    52
#define NPOS       484
#define CAP_DIM    8
#define NUM_MAP    32
#define PP         15488
#define NCLASS     10
#define DDIM       16
#define KTOT       20736        // 256*81
#define NTOT       7744         // 16*484
#define H1N        512
#define H2N        1024
#define RECN       3600

#define OUT_Y_OFF    0
#define OUT_REC_OFF  160
#define OUT_VL_OFF   57760

// ---------------- scratch ----------------
__device__ unsigned       g_x1p[BATCH * F1 * CONV1_H * CONV1_W]; // packed bf16 hi|lo<<16
__device__ unsigned short g_wh [F2 * KTOT];                      // W hi plane
__device__ unsigned short g_wl [F2 * KTOT];                      // W lo plane
__device__ int      g_koff[KTOT];
__device__ float g_pc[BATCH * F2 * NPOS];
__device__ float g_u [BATCH * PP * CAP_DIM];
__device__ float g_bij[BATCH * NCLASS * PP];
__device__ float g_v [BATCH * NCLASS * DDIM];
__device__ float g_wv[BATCH * NCLASS * CAP_DIM];
__device__ float g_m [BATCH * NCLASS * DDIM];
__device__ float g_h1[BATCH * H1N];
__device__ float g_h2[BATCH * H2N];

__device__ __forceinline__ unsigned pack_bf16x2(float v) {
    __nv_bfloat16 h = __float2bfloat16(v);
    float hf = __bfloat162float(h);
    __nv_bfloat16 l = __float2bfloat16(v - hf);
    return (unsigned)__bfloat16_as_ushort(h) | ((unsigned)__bfloat16_as_ushort(l) << 16);
}

__device__ __forceinline__ uint32_t smem_u32(const void* p) {
    uint32_t a;
    asm("{ .reg .u64 t; cvta.to.shared.u64 t, %1; cvt.u32.u64 %0, t; }" : "=r"(a) : "l"(p));
    return a;
}
__device__ __forceinline__ void cpasync16(uint32_t dst, const void* src) {
    asm volatile("cp.async.ca.shared.global [%0], [%1], 16;" :: "r"(dst), "l"(src));
}
__device__ __forceinline__ void cp_commit() {
    asm volatile("cp.async.commit_group;" ::: "memory");
}
template<int N>
__device__ __forceinline__ void cp_wait() {
    asm volatile("cp.async.wait_group %0;" :: "n"(N) : "memory");
}
__device__ __forceinline__ void ldmx4(uint32_t* r, uint32_t addr) {
    asm volatile("ldmatrix.sync.aligned.m8n8.x4.shared.b16 {%0,%1,%2,%3}, [%4];"
                 : "=r"(r[0]), "=r"(r[1]), "=r"(r[2]), "=r"(r[3]) : "r"(addr));
}
__device__ __forceinline__ void mma16816(float* c, const uint32_t* a, const uint32_t* b) {
    asm volatile(
        "mma.sync.aligned.m16n8k16.row.col.f32.bf16.bf16.f32 "
        "{%0,%1,%2,%3}, {%4,%5,%6,%7}, {%8,%9}, {%0,%1,%2,%3};"
        : "+f"(c[0]), "+f"(c[1]), "+f"(c[2]), "+f"(c[3])
        : "r"(a[0]), "r"(a[1]), "r"(a[2]), "r"(a[3]), "r"(b[0]), "r"(b[1]));
}

// ---------------- conv1 + relu -> packed bf16 hi/lo (register window) ------
// thread = (oc local o, x-quad q). ox = 13q + r, r=0..12. Per ky: 21-float
// register window, 9x13 FMAs reuse it -> FMA-bound instead of LDS-bound.
__global__ __launch_bounds__(256) void conv1_kernel(
    const float* __restrict__ img, const float* __restrict__ w,
    const float* __restrict__ bias)
{
    const int ocg = blockIdx.x, oy = blockIdx.y, b = blockIdx.z;
    __shared__ float xs[9][60];
    __shared__ float ws[64 * 81];
    const int tid = threadIdx.x;

    for (int idx = tid; idx < 540; idx += 256) {
        int r = idx / 60, col = idx - r * 60;
        xs[r][col] = img[b * 3600 + (oy + r) * 60 + col];
    }
    for (int idx = tid; idx < 5184; idx += 256)
        ws[idx] = w[ocg * 5184 + idx];
    __syncthreads();

    const int o = tid >> 2;          // local oc 0..63
    const int q = tid & 3;           // x-quad: ox base 13q
    float acc[13];
#pragma unroll
    for (int r = 0; r < 13; r++) acc[r] = 0.f;

#pragma unroll
    for (int ky = 0; ky < 9; ky++) {
        float win[21];
#pragma unroll
        for (int j = 0; j < 21; j++) win[j] = xs[ky][13 * q + j];
#pragma unroll
        for (int kx = 0; kx < 9; kx++) {
            float wv = ws[o * 81 + ky * 9 + kx];
#pragma unroll
            for (int r = 0; r < 13; r++)
                acc[r] += wv * win[r + kx];
        }
    }
    const int oc = ocg * 64 + o;
    const float bia = bias[oc];
    const int base = ((b * F1 + oc) * CONV1_H + oy) * CONV1_W + 13 * q;
#pragma unroll
    for (int r = 0; r < 13; r++)
        g_x1p[base + r] = pack_bf16x2(fmaxf(acc[r] + bia, 0.f));
}

// ---------------- W split + koff table ----------------
__global__ __launch_bounds__(256) void wprep_kernel(const float* __restrict__ w)
{
    int i = blockIdx.x * 256 + threadIdx.x;
    if (i < F2 * KTOT) {
        float v = w[i];
        __nv_bfloat16 h = __float2bfloat16(v);
        float hf = __bfloat162float(h);
        __nv_bfloat16 l = __float2bfloat16(v - hf);
        g_wh[i] = __bfloat16_as_ushort(h);
        g_wl[i] = __bfloat16_as_ushort(l);
    }
    if (i < KTOT) {
        int ci = i / 81, r = i - ci * 81;
        int ky = r / 9, kx = r - ky * 9;
        g_koff[i] = ci * (CONV1_H * CONV1_W) + ky * CONV1_W + kx;
    }
}

// ---------------- pconv: mma.sync bf16 3-pass implicit GEMM (R3 struct) ----
#define BK        32
#define NST       3
#define A_STRIDE  80
#define A_BYTES   (256 * A_STRIDE)
#define B_BYTES   (64 * A_STRIDE)
#define STG       (2 * A_BYTES + 2 * B_BYTES)   // 51200
#define NCHUNK    (KTOT / BK)                   // 648

__global__ __launch_bounds__(256, 1) void pconv_mma_kernel(const float* __restrict__ bias)
{
    extern __shared__ __align__(128) char smem[];
    const uint32_t sb = smem_u32(smem);
    const int tid = threadIdx.x;
    const int lane = tid & 31;
    const int warp = tid >> 5;
    const int wm = warp & 3;
    const int wn = warp >> 2;
    const int pos0 = blockIdx.x * 64;

    const int brow = tid & 63;
    const int bkq  = tid >> 6;
    int nb;
    {
        int n = pos0 + brow;
        int bb = n / NPOS, pos = n - bb * NPOS;
        int oy = pos / 22, ox = pos - oy * 22;
        nb = bb * (F1 * CONV1_H * CONV1_W) + oy * (2 * CONV1_W) + ox * 2;
    }

    float acc[4][4][4];
#pragma unroll
    for (int i = 0; i < 4; i++)
#pragma unroll
        for (int j = 0; j < 4; j++)
#pragma unroll
            for (int q = 0; q < 4; q++) acc[i][j][q] = 0.f;

    auto load_chunk = [&](int s, int i) {
        const int kc = i * BK;
        {
            const unsigned short* srcH = g_wh + (size_t)tid * KTOT + kc;
            const unsigned short* srcL = g_wl + (size_t)tid * KTOT + kc;
            uint32_t dh = sb + s * STG + tid * A_STRIDE;
            uint32_t dl = dh + A_BYTES;
#pragma unroll
            for (int q = 0; q < 4; q++) {
                cpasync16(dh + q * 16, srcH + q * 8);
                cpasync16(dl + q * 16, srcL + q * 8);
            }
        }
        {
            const int* ko = g_koff + kc + bkq * 8;
            int4 k0 = ((const int4*)ko)[0];
            int4 k1 = ((const int4*)ko)[1];
            unsigned p0 = __ldg(&g_x1p[nb + k0.x]);
            unsigned p1 = __ldg(&g_x1p[nb + k0.y]);
            unsigned p2 = __ldg(&g_x1p[nb + k0.z]);
            unsigned p3 = __ldg(&g_x1p[nb + k0.w]);
            unsigned p4 = __ldg(&g_x1p[nb + k1.x]);
            unsigned p5 = __ldg(&g_x1p[nb + k1.y]);
            unsigned p6 = __ldg(&g_x1p[nb + k1.z]);
            unsigned p7 = __ldg(&g_x1p[nb + k1.w]);
            uint4 hi = make_uint4(__byte_perm(p0, p1, 0x5410), __byte_perm(p2, p3, 0x5410),
                                  __byte_perm(p4, p5, 0x5410), __byte_perm(p6, p7, 0x5410));
            uint4 lo = make_uint4(__byte_perm(p0, p1, 0x7632), __byte_perm(p2, p3, 0x7632),
                                  __byte_perm(p4, p5, 0x7632), __byte_perm(p6, p7, 0x7632));
            uint32_t db = s * STG + 2 * A_BYTES + brow * A_STRIDE + bkq * 16;
            *(uint4*)(smem + db) = hi;
            *(uint4*)(smem + db + B_BYTES) = lo;
        }
    };

#pragma unroll
    for (int s = 0; s < NST - 1; s++) {
        load_chunk(s, s);
        cp_commit();
    }

    const uint32_t a_row = (uint32_t)(wm * 64 + (lane & 15));
    const uint32_t a_koff = (uint32_t)((lane >> 4) * 16);
    const uint32_t b_row_base = (uint32_t)(wn * 32 + ((lane >> 4) & 1) * 8 + (lane & 7));
    const uint32_t b_koff = (uint32_t)(((lane >> 3) & 1) * 16);

    for (int i = 0; i < NCHUNK; i++) {
        cp_wait<NST - 2>();
        __syncthreads();
        const int s = i % NST;
        const uint32_t ah_base = sb + s * STG;
        const uint32_t al_base = ah_base + A_BYTES;
        const uint32_t bh_base = ah_base + 2 * A_BYTES;
        const uint32_t bl_base = bh_base + B_BYTES;

#pragma unroll
        for (int kk = 0; kk < 2; kk++) {
            uint32_t a_h[4][4], a_l[4][4], b_h[2][4], b_l[2][4];
#pragma unroll
            for (int mt = 0; mt < 4; mt++) {
                uint32_t off = (a_row + mt * 16) * A_STRIDE + kk * 32 + a_koff;
                ldmx4(a_h[mt], ah_base + off);
                ldmx4(a_l[mt], al_base + off);
            }
#pragma unroll
            for (int nt2 = 0; nt2 < 2; nt2++) {
                uint32_t off = (b_row_base + nt2 * 16) * A_STRIDE + kk * 32 + b_koff;
                ldmx4(b_h[nt2], bh_base + off);
                ldmx4(b_l[nt2], bl_base + off);
            }
#pragma unroll
            for (int mt = 0; mt < 4; mt++) {
#pragma unroll
                for (int nt = 0; nt < 4; nt++) {
                    const uint32_t* bh = &b_h[nt >> 1][(nt & 1) * 2];
                    const uint32_t* bl = &b_l[nt >> 1][(nt & 1) * 2];
                    mma16816(acc[mt][nt], a_h[mt], bh);
                    mma16816(acc[mt][nt], a_h[mt], bl);
                    mma16816(acc[mt][nt], a_l[mt], bh);
                }
            }
        }
        int nx = i + NST - 1;
        if (nx < NCHUNK) load_chunk(nx % NST, nx);
        cp_commit();
    }

    // ---- epilogue ----
    const int g = lane >> 2, t0 = lane & 3;
#pragma unroll
    for (int mt = 0; mt < 4; mt++) {
        int oc0 = wm * 64 + mt * 16 + g;
        float bia0 = bias[oc0], bia1 = bias[oc0 + 8];
#pragma unroll
        for (int nt = 0; nt < 4; nt++) {
            int n0 = pos0 + wn * 32 + nt * 8 + 2 * t0;
#pragma unroll
            for (int e = 0; e < 2; e++) {
                int n = n0 + e;
                int bb = n / NPOS, pos = n - bb * NPOS;
                size_t base = ((size_t)(bb * F2)) * NPOS + pos;
                g_pc[base + (size_t)oc0 * NPOS] = acc[mt][nt][e] + bia0;
                g_pc[base + (size_t)(oc0 + 8) * NPOS] = acc[mt][nt][2 + e] + bia1;
            }
        }
    }
}

// ---------------- gather channels + squash -> u[b][p][8] ----------------
__global__ __launch_bounds__(256) void usquash_kernel()
{
    int i = blockIdx.x * 256 + threadIdx.x;
    if (i >= BATCH * PP) return;
    int b = i / PP, p = i - b * PP;
    int mm = p / NPOS, pos = p - mm * NPOS;
    float uu[8]; float sq = 0.f;
#pragma unroll
    for (int e = 0; e < 8; e++) {
        uu[e] = g_pc[((size_t)b * F2 + e * NUM_MAP + mm) * NPOS + pos];
        sq += uu[e] * uu[e];
    }
    float sc = (sq / (1.f + sq)) * rsqrtf(sq + 1e-8f);
    float4* up = (float4*)(g_u + (size_t)i * 8);
    up[0] = make_float4(uu[0] * sc, uu[1] * sc, uu[2] * sc, uu[3] * sc);
    up[1] = make_float4(uu[4] * sc, uu[5] * sc, uu[6] * sc, uu[7] * sc);
}

// ---------------- routing (1024 thr, shuffle reductions) ----------------
template<bool FIRST>
__global__ __launch_bounds__(1024) void routing_iter(const float* __restrict__ Wd)
{
    const int bc = blockIdx.x;
    const int b = bc / NCLASS, c = bc - b * NCLASS;
    const int tid = threadIdx.x;
    const int lane = tid & 31, wid = tid >> 5;
    __shared__ float swarp[32][10];
    __shared__ float sres[9];
    __shared__ float sM;
    __shared__ float sv16[16];
    __shared__ float sscale;

    const float* bptr = g_bij + (size_t)bc * PP;
    float M = 0.f;
    if (!FIRST) {
        float ml = -1e30f;
        for (int p = tid; p < PP; p += 1024) ml = fmaxf(ml, bptr[p]);
#pragma unroll
        for (int off = 16; off > 0; off >>= 1)
            ml = fmaxf(ml, __shfl_xor_sync(0xffffffffu, ml, off));
        if (lane == 0) swarp[wid][0] = ml;
        __syncthreads();
        if (tid == 0) {
            float mm = swarp[0][0];
            for (int w2 = 1; w2 < 32; w2++) mm = fmaxf(mm, swarp[w2][0]);
            sM = mm;
        }
        __syncthreads();
        M = sM;
    }

    float vals[9];
#pragma unroll
    for (int r = 0; r < 9; r++) vals[r] = 0.f;
    const float4* up = (const float4*)(g_u + (size_t)b * PP * 8);
    for (int p = tid; p < PP; p += 1024) {
        float wgt = FIRST ? 1.f : __expf(bptr[p] - M);
        float4 u0 = up[p * 2], u1 = up[p * 2 + 1];
        vals[0] += wgt;
        vals[1] += wgt * u0.x; vals[2] += wgt * u0.y;
        vals[3] += wgt * u0.z; vals[4] += wgt * u0.w;
        vals[5] += wgt * u1.x; vals[6] += wgt * u1.y;
        vals[7] += wgt * u1.z; vals[8] += wgt * u1.w;
    }
#pragma unroll
    for (int r = 0; r < 9; r++)
#pragma unroll
        for (int off = 16; off > 0; off >>= 1)
            vals[r] += __shfl_xor_sync(0xffffffffu, vals[r], off);
    if (lane == 0)
#pragma unroll
        for (int r = 0; r < 9; r++) swarp[wid][r] = vals[r];
    __syncthreads();
    if (tid < 9) {
        float s = 0.f;
        for (int w2 = 0; w2 < 32; w2++) s += swarp[w2][tid];
        sres[tid] = s;
    }
    __syncthreads();

    const float Zt = sres[0];
    if (tid < DDIM) {
        float s = 0.f;
#pragma unroll
        for (int e = 0; e < 8; e++)
            s += Wd[(c * DDIM + tid) * 8 + e] * (sres[1 + e] / Zt);
        sv16[tid] = s;
    }
    __syncthreads();
    if (tid == 0) {
        float sq = 0.f;
#pragma unroll
        for (int d = 0; d < DDIM; d++) sq += sv16[d] * sv16[d];
        sscale = (sq / (1.f + sq)) * rsqrtf(sq + 1e-8f);
    }
    __syncthreads();
    if (tid < DDIM) {
        float vd = sv16[tid] * sscale;
        g_v[bc * DDIM + tid] = vd;
        sv16[tid] = vd;
    }
    __syncthreads();
    if (tid < CAP_DIM) {
        float w2 = 0.f;
#pragma unroll
        for (int d = 0; d < DDIM; d++)
            w2 += Wd[(c * DDIM + d) * 8 + tid] * sv16[d];
        g_wv[bc * CAP_DIM + tid] = w2;
    }
}

template<bool INIT>
__global__ __launch_bounds__(256) void routing_update()
{
    int i = blockIdx.x * 256 + threadIdx.x;
    if (i >= BATCH * PP) return;
    int b = i / PP, p = i - b * PP;
    const float4* up = (const float4*)(g_u + (size_t)i * 8);
    float4 u0 = up[0], u1 = up[1];
    const float* wvb = g_wv + b * NCLASS * CAP_DIM;
#pragma unroll
    for (int c = 0; c < NCLASS; c++) {
        const float* wv = wvb + c * 8;
        float d = u0.x * wv[0] + u0.y * wv[1] + u0.z * wv[2] + u0.w * wv[3]
                + u1.x * wv[4] + u1.y * wv[5] + u1.z * wv[6] + u1.w * wv[7];
        float* dst = &g_bij[((size_t)(b * NCLASS + c)) * PP + p];
        if (INIT) *dst = d; else *dst += d;
    }
}

// ---------------- finalize ----------------
__global__ void finalize_kernel(float* __restrict__ out)
{
    const int b = blockIdx.x, tid = threadIdx.x;
    __shared__ float svl[NCLASS];
    __shared__ int spred;
    if (tid < NCLASS) {
        float sq = 0.f;
#pragma unroll
        for (int d = 0; d < DDIM; d++) {
            float vv = g_v[(b * NCLASS + tid) * DDIM + d];
            sq += vv * vv;
        }
        svl[tid] = sqrtf(sq);
    }
    __syncthreads();
    if (tid == 0) {
        int pm = 0; float best = svl[0];
        for (int c = 1; c < NCLASS; c++)
            if (svl[c] > best) { best = svl[c]; pm = c; }
        spred = pm;
    }
    __syncthreads();
    if (tid < NCLASS) {
        out[OUT_Y_OFF + b * NCLASS + tid] = (tid == spred) ? 1.0f : 0.0f;
        out[OUT_VL_OFF + b * NCLASS + tid] = svl[tid];
    }
    for (int idx = tid; idx < NCLASS * DDIM; idx += 32) {
        int c = idx >> 4, d = idx & 15;
        g_m[b * NCLASS * DDIM + idx] =
            (c == spred) ? g_v[(b * NCLASS + c) * DDIM + d] : 0.f;
    }
}

// ---------------- decoder ----------------
__global__ __launch_bounds__(256) void dec1_kernel(
    const float* __restrict__ w, const float* __restrict__ bias)
{
    int g = blockIdx.x * 256 + threadIdx.x;
    int b = g >> 9, j = g & 511;
    float acc = bias[j];
#pragma unroll 8
    for (int i = 0; i < 160; i++)
        acc += g_m[b * 160 + i] * w[i * H1N + j];
    g_h1[g] = fmaxf(acc, 0.f);
}

__global__ __launch_bounds__(256) void dec2_kernel(
    const float* __restrict__ w, const float* __restrict__ bias)
{
    int g = blockIdx.x * 256 + threadIdx.x;
    int b = g >> 10, j = g & 1023;
    float acc = bias[j];
#pragma unroll 8
    for (int i = 0; i < H1N; i++)
        acc += g_h1[b * H1N + i] * w[i * H2N + j];
    g_h2[g] = fmaxf(acc, 0.f);
}

__global__ __launch_bounds__(256) void dec3_kernel(
    const float* __restrict__ w, const float* __restrict__ bias,
    float* __restrict__ out)
{
    int jl = threadIdx.x >> 4, b = threadIdx.x & 15;
    int j = blockIdx.x * 16 + jl;
    float acc = bias[j];
#pragma unroll 8
    for (int i = 0; i < H2N; i++)
        acc += g_h2[b * H2N + i] * w[i * RECN + j];
    out[OUT_REC_OFF + b * RECN + j] = 1.f / (1.f + expf(-acc));
}

// ---------------- launch ----------------
extern "C" void kernel_launch(void* const* d_in, const int* in_sizes, int n_in,
                              void* d_out, int out_size)
{
    const float* imgs    = (const float*)d_in[0];
    const float* conv1_w = (const float*)d_in[1];
    const float* conv1_b = (const float*)d_in[2];
    const float* pconv_w = (const float*)d_in[3];
    const float* pconv_b = (const float*)d_in[4];
    const float* W_digit = (const float*)d_in[5];
    const float* dec_w1  = (const float*)d_in[6];
    const float* dec_b1  = (const float*)d_in[7];
    const float* dec_w2  = (const float*)d_in[8];
    const float* dec_b2  = (const float*)d_in[9];
    const float* dec_w3  = (const float*)d_in[10];
    const float* dec_b3  = (const float*)d_in[11];
    float* out = (float*)d_out;

    const int smem_bytes = NST * STG;   // 153600
    cudaFuncSetAttribute(pconv_mma_kernel,
                         cudaFuncAttributeMaxDynamicSharedMemorySize, smem_bytes);

    conv1_kernel<<<dim3(4, CONV1_H, BATCH), 256>>>(imgs, conv1_w, conv1_b);
    wprep_kernel<<<(F2 * KTOT + 255) / 256, 256>>>(pconv_w);
    pconv_mma_kernel<<<NTOT / 64, 256, smem_bytes>>>(pconv_b);
    usquash_kernel<<<(BATCH * PP) / 256, 256>>>();

    routing_iter<true><<<BATCH * NCLASS, 1024>>>(W_digit);
    routing_update<true><<<(BATCH * PP) / 256, 256>>>();
    routing_iter<false><<<BATCH * NCLASS, 1024>>>(W_digit);
    routing_update<false><<<(BATCH * PP) / 256, 256>>>();
    routing_iter<false><<<BATCH * NCLASS, 1024>>>(W_digit);

    finalize_kernel<<<BATCH, 32>>>(out);
    dec1_kernel<<<(BATCH * H1N) / 256, 256>>>(dec_w1, dec_b1);
    dec2_kernel<<<(BATCH * H2N) / 256, 256>>>(dec_w2, dec_b2);
    dec3_kernel<<<RECN / 16, 256>>>(dec_w3, dec_b3, out);
}

// round 6
// speedup vs baseline: 1.2000x; 1.1437x over previous
#include <cuda_runtime.h>
#include <cuda_bf16.h>
#include <cstdint>
#include <math.h>

// ---------------- problem constants ----------------
#define BATCH      16
#define IMG_H      60
#define IMG_W      60
#define F1         256
#define F2         256
#define CONV1_H    52
#define CONV1_W    52
#define NPOS       484
#define CAP_DIM    8
#define NUM_MAP    32
#define PP         15488
#define NCLASS     10
#define DDIM       16
#define KTOT       20736        // 256*81
#define NTOT       7744         // 16*484
#define H1N        512
#define H2N        1024
#define RECN       3600
#define KSPLIT     6

#define OUT_Y_OFF    0
#define OUT_REC_OFF  160
#define OUT_VL_OFF   57760

// ---------------- scratch ----------------
__device__ unsigned       g_x1p[BATCH * F1 * CONV1_H * CONV1_W]; // packed bf16 hi|lo<<16
__device__ unsigned short g_wh [F2 * KTOT];                      // W hi plane
__device__ unsigned short g_wl [F2 * KTOT];                      // W lo plane
__device__ int      g_koff[KTOT];
__device__ float g_pcp[KSPLIT * F2 * NTOT];                      // K-split partials [s][oc][n]
__device__ float g_u [BATCH * PP * CAP_DIM];
__device__ float g_bij[BATCH * NCLASS * PP];
__device__ float g_v [BATCH * NCLASS * DDIM];
__device__ float g_wv[BATCH * NCLASS * CAP_DIM];
__device__ float g_m [BATCH * NCLASS * DDIM];
__device__ float g_h1[BATCH * H1N];
__device__ float g_h2[BATCH * H2N];

__device__ __forceinline__ unsigned pack_bf16x2(float v) {
    __nv_bfloat16 h = __float2bfloat16(v);
    float hf = __bfloat162float(h);
    __nv_bfloat16 l = __float2bfloat16(v - hf);
    return (unsigned)__bfloat16_as_ushort(h) | ((unsigned)__bfloat16_as_ushort(l) << 16);
}

__device__ __forceinline__ uint32_t smem_u32(const void* p) {
    uint32_t a;
    asm("{ .reg .u64 t; cvta.to.shared.u64 t, %1; cvt.u32.u64 %0, t; }" : "=r"(a) : "l"(p));
    return a;
}
__device__ __forceinline__ void cpasync16(uint32_t dst, const void* src) {
    asm volatile("cp.async.ca.shared.global [%0], [%1], 16;" :: "r"(dst), "l"(src));
}
__device__ __forceinline__ void cp_commit() {
    asm volatile("cp.async.commit_group;" ::: "memory");
}
template<int N>
__device__ __forceinline__ void cp_wait() {
    asm volatile("cp.async.wait_group %0;" :: "n"(N) : "memory");
}
__device__ __forceinline__ void ldmx4(uint32_t* r, uint32_t addr) {
    asm volatile("ldmatrix.sync.aligned.m8n8.x4.shared.b16 {%0,%1,%2,%3}, [%4];"
                 : "=r"(r[0]), "=r"(r[1]), "=r"(r[2]), "=r"(r[3]) : "r"(addr));
}
__device__ __forceinline__ void mma16816(float* c, const uint32_t* a, const uint32_t* b) {
    asm volatile(
        "mma.sync.aligned.m16n8k16.row.col.f32.bf16.bf16.f32 "
        "{%0,%1,%2,%3}, {%4,%5,%6,%7}, {%8,%9}, {%0,%1,%2,%3};"
        : "+f"(c[0]), "+f"(c[1]), "+f"(c[2]), "+f"(c[3])
        : "r"(a[0]), "r"(a[1]), "r"(a[2]), "r"(a[3]), "r"(b[0]), "r"(b[1]));
}

// ---------------- conv1 + relu -> packed bf16 hi/lo ----------------
__global__ __launch_bounds__(256) void conv1_kernel(
    const float* __restrict__ img, const float* __restrict__ w,
    const float* __restrict__ bias)
{
    const int ocg = blockIdx.x, oy = blockIdx.y, b = blockIdx.z;
    __shared__ float xs[9][60];
    __shared__ float ws[64 * 81];
    const int tid = threadIdx.x;

    for (int idx = tid; idx < 540; idx += 256) {
        int r = idx / 60, col = idx - r * 60;
        xs[r][col] = img[b * 3600 + (oy + r) * 60 + col];
    }
    for (int idx = tid; idx < 5184; idx += 256)
        ws[idx] = w[ocg * 5184 + idx];
    __syncthreads();

    const int o = tid >> 2;
    const int q = tid & 3;
    float acc[13];
#pragma unroll
    for (int r = 0; r < 13; r++) acc[r] = 0.f;

#pragma unroll
    for (int ky = 0; ky < 9; ky++) {
        float win[21];
#pragma unroll
        for (int j = 0; j < 21; j++) win[j] = xs[ky][13 * q + j];
#pragma unroll
        for (int kx = 0; kx < 9; kx++) {
            float wv = ws[o * 81 + ky * 9 + kx];
#pragma unroll
            for (int r = 0; r < 13; r++)
                acc[r] += wv * win[r + kx];
        }
    }
    const int oc = ocg * 64 + o;
    const float bia = bias[oc];
    const int base = ((b * F1 + oc) * CONV1_H + oy) * CONV1_W + 13 * q;
#pragma unroll
    for (int r = 0; r < 13; r++)
        g_x1p[base + r] = pack_bf16x2(fmaxf(acc[r] + bia, 0.f));
}

// ---------------- W split + koff table ----------------
__global__ __launch_bounds__(256) void wprep_kernel(const float* __restrict__ w)
{
    int i = blockIdx.x * 256 + threadIdx.x;
    if (i < F2 * KTOT) {
        float v = w[i];
        __nv_bfloat16 h = __float2bfloat16(v);
        float hf = __bfloat162float(h);
        __nv_bfloat16 l = __float2bfloat16(v - hf);
        g_wh[i] = __bfloat16_as_ushort(h);
        g_wl[i] = __bfloat16_as_ushort(l);
    }
    if (i < KTOT) {
        int ci = i / 81, r = i - ci * 81;
        int ky = r / 9, kx = r - ky * 9;
        g_koff[i] = ci * (CONV1_H * CONV1_W) + ky * CONV1_W + kx;
    }
}

// ---------------- pconv: mma.sync bf16 3-pass, 6-way K-split ----------------
#define BK        32
#define NST       3
#define A_STRIDE  80
#define A_BYTES   (256 * A_STRIDE)
#define B_BYTES   (64 * A_STRIDE)
#define STG       (2 * A_BYTES + 2 * B_BYTES)   // 51200
#define NCHUNK    (KTOT / BK)                   // 648
#define CPS       (NCHUNK / KSPLIT)             // 108 chunks per CTA

__global__ __launch_bounds__(256, 1) void pconv_mma_kernel()
{
    extern __shared__ __align__(128) char smem[];
    const uint32_t sb = smem_u32(smem);
    const int tid = threadIdx.x;
    const int lane = tid & 31;
    const int warp = tid >> 5;
    const int wm = warp & 3;
    const int wn = warp >> 2;
    const int pos0 = blockIdx.x * 64;
    const int ks   = blockIdx.y;            // K-split index
    const int cbase = ks * CPS;             // first chunk

    const int brow = tid & 63;
    const int bkq  = tid >> 6;
    int nb;
    {
        int n = pos0 + brow;
        int bb = n / NPOS, pos = n - bb * NPOS;
        int oy = pos / 22, ox = pos - oy * 22;
        nb = bb * (F1 * CONV1_H * CONV1_W) + oy * (2 * CONV1_W) + ox * 2;
    }

    float acc[4][4][4];
#pragma unroll
    for (int i = 0; i < 4; i++)
#pragma unroll
        for (int j = 0; j < 4; j++)
#pragma unroll
            for (int q = 0; q < 4; q++) acc[i][j][q] = 0.f;

    auto load_chunk = [&](int s, int i) {
        const int kc = (cbase + i) * BK;
        {
            const unsigned short* srcH = g_wh + (size_t)tid * KTOT + kc;
            const unsigned short* srcL = g_wl + (size_t)tid * KTOT + kc;
            uint32_t dh = sb + s * STG + tid * A_STRIDE;
            uint32_t dl = dh + A_BYTES;
#pragma unroll
            for (int q = 0; q < 4; q++) {
                cpasync16(dh + q * 16, srcH + q * 8);
                cpasync16(dl + q * 16, srcL + q * 8);
            }
        }
        {
            const int* ko = g_koff + kc + bkq * 8;
            int4 k0 = ((const int4*)ko)[0];
            int4 k1 = ((const int4*)ko)[1];
            unsigned p0 = __ldg(&g_x1p[nb + k0.x]);
            unsigned p1 = __ldg(&g_x1p[nb + k0.y]);
            unsigned p2 = __ldg(&g_x1p[nb + k0.z]);
            unsigned p3 = __ldg(&g_x1p[nb + k0.w]);
            unsigned p4 = __ldg(&g_x1p[nb + k1.x]);
            unsigned p5 = __ldg(&g_x1p[nb + k1.y]);
            unsigned p6 = __ldg(&g_x1p[nb + k1.z]);
            unsigned p7 = __ldg(&g_x1p[nb + k1.w]);
            uint4 hi = make_uint4(__byte_perm(p0, p1, 0x5410), __byte_perm(p2, p3, 0x5410),
                                  __byte_perm(p4, p5, 0x5410), __byte_perm(p6, p7, 0x5410));
            uint4 lo = make_uint4(__byte_perm(p0, p1, 0x7632), __byte_perm(p2, p3, 0x7632),
                                  __byte_perm(p4, p5, 0x7632), __byte_perm(p6, p7, 0x7632));
            uint32_t db = s * STG + 2 * A_BYTES + brow * A_STRIDE + bkq * 16;
            *(uint4*)(smem + db) = hi;
            *(uint4*)(smem + db + B_BYTES) = lo;
        }
    };

#pragma unroll
    for (int s = 0; s < NST - 1; s++) {
        load_chunk(s, s);
        cp_commit();
    }

    const uint32_t a_row = (uint32_t)(wm * 64 + (lane & 15));
    const uint32_t a_koff = (uint32_t)((lane >> 4) * 16);
    const uint32_t b_row_base = (uint32_t)(wn * 32 + ((lane >> 4) & 1) * 8 + (lane & 7));
    const uint32_t b_koff = (uint32_t)(((lane >> 3) & 1) * 16);

    for (int i = 0; i < CPS; i++) {
        cp_wait<NST - 2>();
        __syncthreads();
        const int s = i % NST;
        const uint32_t ah_base = sb + s * STG;
        const uint32_t al_base = ah_base + A_BYTES;
        const uint32_t bh_base = ah_base + 2 * A_BYTES;
        const uint32_t bl_base = bh_base + B_BYTES;

#pragma unroll
        for (int kk = 0; kk < 2; kk++) {
            uint32_t a_h[4][4], a_l[4][4], b_h[2][4], b_l[2][4];
#pragma unroll
            for (int mt = 0; mt < 4; mt++) {
                uint32_t off = (a_row + mt * 16) * A_STRIDE + kk * 32 + a_koff;
                ldmx4(a_h[mt], ah_base + off);
                ldmx4(a_l[mt], al_base + off);
            }
#pragma unroll
            for (int nt2 = 0; nt2 < 2; nt2++) {
                uint32_t off = (b_row_base + nt2 * 16) * A_STRIDE + kk * 32 + b_koff;
                ldmx4(b_h[nt2], bh_base + off);
                ldmx4(b_l[nt2], bl_base + off);
            }
#pragma unroll
            for (int mt = 0; mt < 4; mt++) {
#pragma unroll
                for (int nt = 0; nt < 4; nt++) {
                    const uint32_t* bh = &b_h[nt >> 1][(nt & 1) * 2];
                    const uint32_t* bl = &b_l[nt >> 1][(nt & 1) * 2];
                    mma16816(acc[mt][nt], a_h[mt], bh);
                    mma16816(acc[mt][nt], a_h[mt], bl);
                    mma16816(acc[mt][nt], a_l[mt], bh);
                }
            }
        }
        int nx = i + NST - 1;
        if (nx < CPS) load_chunk(nx % NST, nx);
        cp_commit();
    }

    // ---- epilogue: write partial [ks][oc][n], n-major (no scatter) ----
    const int g = lane >> 2, t0 = lane & 3;
#pragma unroll
    for (int mt = 0; mt < 4; mt++) {
        int oc0 = wm * 64 + mt * 16 + g;
#pragma unroll
        for (int nt = 0; nt < 4; nt++) {
            int n0 = pos0 + wn * 32 + nt * 8 + 2 * t0;
            float* d0 = g_pcp + ((size_t)ks * F2 + oc0) * NTOT + n0;
            *(float2*)d0 = make_float2(acc[mt][nt][0], acc[mt][nt][1]);
            *(float2*)(d0 + (size_t)8 * NTOT) = make_float2(acc[mt][nt][2], acc[mt][nt][3]);
        }
    }
}

// ---------------- fused K-combine + bias + channel gather + squash ---------
__global__ __launch_bounds__(256) void usquash_kernel(const float* __restrict__ bias)
{
    int i = blockIdx.x * 256 + threadIdx.x;
    if (i >= BATCH * PP) return;
    int b = i / PP, p = i - b * PP;
    int mm = p / NPOS, pos = p - mm * NPOS;
    int n = b * NPOS + pos;
    float uu[8]; float sq = 0.f;
#pragma unroll
    for (int e = 0; e < 8; e++) {
        int oc = e * NUM_MAP + mm;
        const float* q = g_pcp + (size_t)oc * NTOT + n;
        float v = bias[oc];
#pragma unroll
        for (int s = 0; s < KSPLIT; s++)
            v += q[(size_t)s * F2 * NTOT];
        uu[e] = v;
        sq += v * v;
    }
    float sc = (sq / (1.f + sq)) * rsqrtf(sq + 1e-8f);
    float4* up = (float4*)(g_u + (size_t)i * 8);
    up[0] = make_float4(uu[0] * sc, uu[1] * sc, uu[2] * sc, uu[3] * sc);
    up[1] = make_float4(uu[4] * sc, uu[5] * sc, uu[6] * sc, uu[7] * sc);
}

// ---------------- routing (1024 thr, shuffle reductions) ----------------
template<bool FIRST>
__global__ __launch_bounds__(1024) void routing_iter(const float* __restrict__ Wd)
{
    const int bc = blockIdx.x;
    const int b = bc / NCLASS, c = bc - b * NCLASS;
    const int tid = threadIdx.x;
    const int lane = tid & 31, wid = tid >> 5;
    __shared__ float swarp[32][10];
    __shared__ float sres[9];
    __shared__ float sM;
    __shared__ float sv16[16];
    __shared__ float sscale;

    const float* bptr = g_bij + (size_t)bc * PP;
    float M = 0.f;
    if (!FIRST) {
        float ml = -1e30f;
        for (int p = tid; p < PP; p += 1024) ml = fmaxf(ml, bptr[p]);
#pragma unroll
        for (int off = 16; off > 0; off >>= 1)
            ml = fmaxf(ml, __shfl_xor_sync(0xffffffffu, ml, off));
        if (lane == 0) swarp[wid][0] = ml;
        __syncthreads();
        if (tid == 0) {
            float mm = swarp[0][0];
            for (int w2 = 1; w2 < 32; w2++) mm = fmaxf(mm, swarp[w2][0]);
            sM = mm;
        }
        __syncthreads();
        M = sM;
    }

    float vals[9];
#pragma unroll
    for (int r = 0; r < 9; r++) vals[r] = 0.f;
    const float4* up = (const float4*)(g_u + (size_t)b * PP * 8);
    for (int p = tid; p < PP; p += 1024) {
        float wgt = FIRST ? 1.f : __expf(bptr[p] - M);
        float4 u0 = up[p * 2], u1 = up[p * 2 + 1];
        vals[0] += wgt;
        vals[1] += wgt * u0.x; vals[2] += wgt * u0.y;
        vals[3] += wgt * u0.z; vals[4] += wgt * u0.w;
        vals[5] += wgt * u1.x; vals[6] += wgt * u1.y;
        vals[7] += wgt * u1.z; vals[8] += wgt * u1.w;
    }
#pragma unroll
    for (int r = 0; r < 9; r++)
#pragma unroll
        for (int off = 16; off > 0; off >>= 1)
            vals[r] += __shfl_xor_sync(0xffffffffu, vals[r], off);
    if (lane == 0)
#pragma unroll
        for (int r = 0; r < 9; r++) swarp[wid][r] = vals[r];
    __syncthreads();
    if (tid < 9) {
        float s = 0.f;
        for (int w2 = 0; w2 < 32; w2++) s += swarp[w2][tid];
        sres[tid] = s;
    }
    __syncthreads();

    const float Zt = sres[0];
    if (tid < DDIM) {
        float s = 0.f;
#pragma unroll
        for (int e = 0; e < 8; e++)
            s += Wd[(c * DDIM + tid) * 8 + e] * (sres[1 + e] / Zt);
        sv16[tid] = s;
    }
    __syncthreads();
    if (tid == 0) {
        float sq = 0.f;
#pragma unroll
        for (int d = 0; d < DDIM; d++) sq += sv16[d] * sv16[d];
        sscale = (sq / (1.f + sq)) * rsqrtf(sq + 1e-8f);
    }
    __syncthreads();
    if (tid < DDIM) {
        float vd = sv16[tid] * sscale;
        g_v[bc * DDIM + tid] = vd;
        sv16[tid] = vd;
    }
    __syncthreads();
    if (tid < CAP_DIM) {
        float w2 = 0.f;
#pragma unroll
        for (int d = 0; d < DDIM; d++)
            w2 += Wd[(c * DDIM + d) * 8 + tid] * sv16[d];
        g_wv[bc * CAP_DIM + tid] = w2;
    }
}

template<bool INIT>
__global__ __launch_bounds__(256) void routing_update()
{
    int i = blockIdx.x * 256 + threadIdx.x;
    if (i >= BATCH * PP) return;
    int b = i / PP, p = i - b * PP;
    const float4* up = (const float4*)(g_u + (size_t)i * 8);
    float4 u0 = up[0], u1 = up[1];
    const float* wvb = g_wv + b * NCLASS * CAP_DIM;
#pragma unroll
    for (int c = 0; c < NCLASS; c++) {
        const float* wv = wvb + c * 8;
        float d = u0.x * wv[0] + u0.y * wv[1] + u0.z * wv[2] + u0.w * wv[3]
                + u1.x * wv[4] + u1.y * wv[5] + u1.z * wv[6] + u1.w * wv[7];
        float* dst = &g_bij[((size_t)(b * NCLASS + c)) * PP + p];
        if (INIT) *dst = d; else *dst += d;
    }
}

// ---------------- finalize ----------------
__global__ void finalize_kernel(float* __restrict__ out)
{
    const int b = blockIdx.x, tid = threadIdx.x;
    __shared__ float svl[NCLASS];
    __shared__ int spred;
    if (tid < NCLASS) {
        float sq = 0.f;
#pragma unroll
        for (int d = 0; d < DDIM; d++) {
            float vv = g_v[(b * NCLASS + tid) * DDIM + d];
            sq += vv * vv;
        }
        svl[tid] = sqrtf(sq);
    }
    __syncthreads();
    if (tid == 0) {
        int pm = 0; float best = svl[0];
        for (int c = 1; c < NCLASS; c++)
            if (svl[c] > best) { best = svl[c]; pm = c; }
        spred = pm;
    }
    __syncthreads();
    if (tid < NCLASS) {
        out[OUT_Y_OFF + b * NCLASS + tid] = (tid == spred) ? 1.0f : 0.0f;
        out[OUT_VL_OFF + b * NCLASS + tid] = svl[tid];
    }
    for (int idx = tid; idx < NCLASS * DDIM; idx += 32) {
        int c = idx >> 4, d = idx & 15;
        g_m[b * NCLASS * DDIM + idx] =
            (c == spred) ? g_v[(b * NCLASS + c) * DDIM + d] : 0.f;
    }
}

// ---------------- decoder ----------------
__global__ __launch_bounds__(256) void dec1_kernel(
    const float* __restrict__ w, const float* __restrict__ bias)
{
    int g = blockIdx.x * 256 + threadIdx.x;
    int b = g >> 9, j = g & 511;
    float acc = bias[j];
#pragma unroll 8
    for (int i = 0; i < 160; i++)
        acc += g_m[b * 160 + i] * w[i * H1N + j];
    g_h1[g] = fmaxf(acc, 0.f);
}

__global__ __launch_bounds__(256) void dec2_kernel(
    const float* __restrict__ w, const float* __restrict__ bias)
{
    int g = blockIdx.x * 256 + threadIdx.x;
    int b = g >> 10, j = g & 1023;
    float acc = bias[j];
#pragma unroll 8
    for (int i = 0; i < H1N; i++)
        acc += g_h1[b * H1N + i] * w[i * H2N + j];
    g_h2[g] = fmaxf(acc, 0.f);
}

__global__ __launch_bounds__(256) void dec3_kernel(
    const float* __restrict__ w, const float* __restrict__ bias,
    float* __restrict__ out)
{
    int jl = threadIdx.x >> 4, b = threadIdx.x & 15;
    int j = blockIdx.x * 16 + jl;
    float acc = bias[j];
#pragma unroll 8
    for (int i = 0; i < H2N; i++)
        acc += g_h2[b * H2N + i] * w[i * RECN + j];
    out[OUT_REC_OFF + b * RECN + j] = 1.f / (1.f + expf(-acc));
}

// ---------------- launch ----------------
extern "C" void kernel_launch(void* const* d_in, const int* in_sizes, int n_in,
                              void* d_out, int out_size)
{
    const float* imgs    = (const float*)d_in[0];
    const float* conv1_w = (const float*)d_in[1];
    const float* conv1_b = (const float*)d_in[2];
    const float* pconv_w = (const float*)d_in[3];
    const float* pconv_b = (const float*)d_in[4];
    const float* W_digit = (const float*)d_in[5];
    const float* dec_w1  = (const float*)d_in[6];
    const float* dec_b1  = (const float*)d_in[7];
    const float* dec_w2  = (const float*)d_in[8];
    const float* dec_b2  = (const float*)d_in[9];
    const float* dec_w3  = (const float*)d_in[10];
    const float* dec_b3  = (const float*)d_in[11];
    float* out = (float*)d_out;

    const int smem_bytes = NST * STG;   // 153600
    cudaFuncSetAttribute(pconv_mma_kernel,
                         cudaFuncAttributeMaxDynamicSharedMemorySize, smem_bytes);

    conv1_kernel<<<dim3(4, CONV1_H, BATCH), 256>>>(imgs, conv1_w, conv1_b);
    wprep_kernel<<<(F2 * KTOT + 255) / 256, 256>>>(pconv_w);
    pconv_mma_kernel<<<dim3(NTOT / 64, KSPLIT), 256, smem_bytes>>>();
    usquash_kernel<<<(BATCH * PP) / 256, 256>>>(pconv_b);

    routing_iter<true><<<BATCH * NCLASS, 1024>>>(W_digit);
    routing_update<true><<<(BATCH * PP) / 256, 256>>>();
    routing_iter<false><<<BATCH * NCLASS, 1024>>>(W_digit);
    routing_update<false><<<(BATCH * PP) / 256, 256>>>();
    routing_iter<false><<<BATCH * NCLASS, 1024>>>(W_digit);

    finalize_kernel<<<BATCH, 32>>>(out);
    dec1_kernel<<<(BATCH * H1N) / 256, 256>>>(dec_w1, dec_b1);
    dec2_kernel<<<(BATCH * H2N) / 256, 256>>>(dec_w2, dec_b2);
    dec3_kernel<<<RECN / 16, 256>>>(dec_w3, dec_b3, out);
}

// round 7
// speedup vs baseline: 1.7452x; 1.4543x over previous
#include <cuda_runtime.h>
#include <cuda_fp16.h>
#include <cstdint>
#include <math.h>

// ---------------- problem constants ----------------
#define BATCH      16
#define IMG_H      60
#define IMG_W      60
#define F1         256
#define F2         256
#define CONV1_H    52
#define CONV1_W    52
#define NPOS       484
#define CAP_DIM    8
#define NUM_MAP    32
#define PP         15488
#define NCLASS     10
#define DDIM       16
#define KTOT       20736        // 256*81
#define NTOT       7744         // 16*484
#define H1N        512
#define H2N        1024
#define RECN       3600
#define KSPLIT     6

#define OUT_Y_OFF    0
#define OUT_REC_OFF  160
#define OUT_VL_OFF   57760

// ---------------- scratch ----------------
__device__ unsigned short g_x1h[BATCH * F1 * CONV1_H * CONV1_W]; // conv1 out, fp16 bits
__device__ unsigned short g_w16[F2 * KTOT];                      // W fp16 bits
__device__ int      g_koff[KTOT];
__device__ float g_pcp[KSPLIT * F2 * NTOT];                      // K-split partials [s][oc][n]
__device__ float g_u [BATCH * PP * CAP_DIM];
__device__ float g_bij[BATCH * NCLASS * PP];
__device__ float g_v [BATCH * NCLASS * DDIM];
__device__ float g_wv[BATCH * NCLASS * CAP_DIM];
__device__ float g_m [BATCH * NCLASS * DDIM];
__device__ float g_h1[BATCH * H1N];
__device__ float g_h2[BATCH * H2N];

__device__ __forceinline__ uint32_t smem_u32(const void* p) {
    uint32_t a;
    asm("{ .reg .u64 t; cvta.to.shared.u64 t, %1; cvt.u32.u64 %0, t; }" : "=r"(a) : "l"(p));
    return a;
}
__device__ __forceinline__ void cpasync16(uint32_t dst, const void* src) {
    asm volatile("cp.async.ca.shared.global [%0], [%1], 16;" :: "r"(dst), "l"(src));
}
__device__ __forceinline__ void cp_commit() {
    asm volatile("cp.async.commit_group;" ::: "memory");
}
template<int N>
__device__ __forceinline__ void cp_wait() {
    asm volatile("cp.async.wait_group %0;" :: "n"(N) : "memory");
}
__device__ __forceinline__ void ldmx4(uint32_t* r, uint32_t addr) {
    asm volatile("ldmatrix.sync.aligned.m8n8.x4.shared.b16 {%0,%1,%2,%3}, [%4];"
                 : "=r"(r[0]), "=r"(r[1]), "=r"(r[2]), "=r"(r[3]) : "r"(addr));
}
__device__ __forceinline__ void mma16816h(float* c, const uint32_t* a, const uint32_t* b) {
    asm volatile(
        "mma.sync.aligned.m16n8k16.row.col.f32.f16.f16.f32 "
        "{%0,%1,%2,%3}, {%4,%5,%6,%7}, {%8,%9}, {%0,%1,%2,%3};"
        : "+f"(c[0]), "+f"(c[1]), "+f"(c[2]), "+f"(c[3])
        : "r"(a[0]), "r"(a[1]), "r"(a[2]), "r"(a[3]), "r"(b[0]), "r"(b[1]));
}

// ---------------- conv1 + relu -> fp16 ----------------
__global__ __launch_bounds__(256) void conv1_kernel(
    const float* __restrict__ img, const float* __restrict__ w,
    const float* __restrict__ bias)
{
    const int ocg = blockIdx.x, oy = blockIdx.y, b = blockIdx.z;
    __shared__ float xs[9][60];
    __shared__ float ws[64 * 81];
    const int tid = threadIdx.x;

    for (int idx = tid; idx < 540; idx += 256) {
        int r = idx / 60, col = idx - r * 60;
        xs[r][col] = img[b * 3600 + (oy + r) * 60 + col];
    }
    for (int idx = tid; idx < 5184; idx += 256)
        ws[idx] = w[ocg * 5184 + idx];
    __syncthreads();

    const int o = tid >> 2;
    const int q = tid & 3;
    float acc[13];
#pragma unroll
    for (int r = 0; r < 13; r++) acc[r] = 0.f;

#pragma unroll
    for (int ky = 0; ky < 9; ky++) {
        float win[21];
#pragma unroll
        for (int j = 0; j < 21; j++) win[j] = xs[ky][13 * q + j];
#pragma unroll
        for (int kx = 0; kx < 9; kx++) {
            float wv = ws[o * 81 + ky * 9 + kx];
#pragma unroll
            for (int r = 0; r < 13; r++)
                acc[r] += wv * win[r + kx];
        }
    }
    const int oc = ocg * 64 + o;
    const float bia = bias[oc];
    const int base = ((b * F1 + oc) * CONV1_H + oy) * CONV1_W + 13 * q;
#pragma unroll
    for (int r = 0; r < 13; r++)
        g_x1h[base + r] = __half_as_ushort(__float2half_rn(fmaxf(acc[r] + bia, 0.f)));
}

// ---------------- W fp16 + koff table ----------------
__global__ __launch_bounds__(256) void wprep_kernel(const float* __restrict__ w)
{
    int i = blockIdx.x * 256 + threadIdx.x;
    if (i < F2 * KTOT)
        g_w16[i] = __half_as_ushort(__float2half_rn(w[i]));
    if (i < KTOT) {
        int ci = i / 81, r = i - ci * 81;
        int ky = r / 9, kx = r - ky * 9;
        g_koff[i] = ci * (CONV1_H * CONV1_W) + ky * CONV1_W + kx;
    }
}

// ---------------- pconv: single-pass fp16 mma.sync, 6-way K-split ----------
#define BK        32
#define NST       4
#define A_STRIDE  80
#define A_BYTES   (256 * A_STRIDE)              // 20480
#define B_BYTES   (64 * A_STRIDE)               // 5120
#define STG       (A_BYTES + B_BYTES)           // 25600
#define NCHUNK    (KTOT / BK)                   // 648
#define CPS       (NCHUNK / KSPLIT)             // 108 chunks per CTA

__global__ __launch_bounds__(256, 1) void pconv_mma_kernel()
{
    extern __shared__ __align__(128) char smem[];
    const uint32_t sb = smem_u32(smem);
    const int tid = threadIdx.x;
    const int lane = tid & 31;
    const int warp = tid >> 5;
    const int wm = warp & 3;
    const int wn = warp >> 2;
    const int pos0 = blockIdx.x * 64;
    const int ks   = blockIdx.y;
    const int cbase = ks * CPS;

    const int brow = tid & 63;
    const int bkq  = tid >> 6;
    int nb;
    {
        int n = pos0 + brow;
        int bb = n / NPOS, pos = n - bb * NPOS;
        int oy = pos / 22, ox = pos - oy * 22;
        nb = bb * (F1 * CONV1_H * CONV1_W) + oy * (2 * CONV1_W) + ox * 2;
    }

    float acc[4][4][4];
#pragma unroll
    for (int i = 0; i < 4; i++)
#pragma unroll
        for (int j = 0; j < 4; j++)
#pragma unroll
            for (int q = 0; q < 4; q++) acc[i][j][q] = 0.f;

    auto load_chunk = [&](int s, int i) {
        const int kc = (cbase + i) * BK;
        {   // A: row tid, 32 fp16 = 64B via 4x cp.async 16B
            const unsigned short* src = g_w16 + (size_t)tid * KTOT + kc;
            uint32_t dh = sb + s * STG + tid * A_STRIDE;
#pragma unroll
            for (int q = 0; q < 4; q++)
                cpasync16(dh + q * 16, src + q * 8);
        }
        {   // B: row brow, k octet bkq (8 fp16 = 16B)
            const int* ko = g_koff + kc + bkq * 8;
            int4 k0 = ((const int4*)ko)[0];
            int4 k1 = ((const int4*)ko)[1];
            unsigned p0 = __ldg(&g_x1h[nb + k0.x]);
            unsigned p1 = __ldg(&g_x1h[nb + k0.y]);
            unsigned p2 = __ldg(&g_x1h[nb + k0.z]);
            unsigned p3 = __ldg(&g_x1h[nb + k0.w]);
            unsigned p4 = __ldg(&g_x1h[nb + k1.x]);
            unsigned p5 = __ldg(&g_x1h[nb + k1.y]);
            unsigned p6 = __ldg(&g_x1h[nb + k1.z]);
            unsigned p7 = __ldg(&g_x1h[nb + k1.w]);
            uint4 v = make_uint4(p0 | (p1 << 16), p2 | (p3 << 16),
                                 p4 | (p5 << 16), p6 | (p7 << 16));
            uint32_t db = s * STG + A_BYTES + brow * A_STRIDE + bkq * 16;
            *(uint4*)(smem + db) = v;
        }
    };

#pragma unroll
    for (int s = 0; s < NST - 1; s++) {
        load_chunk(s, s);
        cp_commit();
    }

    const uint32_t a_row = (uint32_t)(wm * 64 + (lane & 15));
    const uint32_t a_koff = (uint32_t)((lane >> 4) * 16);
    const uint32_t b_row_base = (uint32_t)(wn * 32 + ((lane >> 4) & 1) * 8 + (lane & 7));
    const uint32_t b_koff = (uint32_t)(((lane >> 3) & 1) * 16);

    for (int i = 0; i < CPS; i++) {
        cp_wait<NST - 2>();
        __syncthreads();
        const int s = i % NST;
        const uint32_t a_base = sb + s * STG;
        const uint32_t b_base = a_base + A_BYTES;

#pragma unroll
        for (int kk = 0; kk < 2; kk++) {
            uint32_t a_f[4][4], b_f[2][4];
#pragma unroll
            for (int mt = 0; mt < 4; mt++)
                ldmx4(a_f[mt], a_base + (a_row + mt * 16) * A_STRIDE + kk * 32 + a_koff);
#pragma unroll
            for (int nt2 = 0; nt2 < 2; nt2++)
                ldmx4(b_f[nt2], b_base + (b_row_base + nt2 * 16) * A_STRIDE + kk * 32 + b_koff);
#pragma unroll
            for (int mt = 0; mt < 4; mt++)
#pragma unroll
                for (int nt = 0; nt < 4; nt++)
                    mma16816h(acc[mt][nt], a_f[mt], &b_f[nt >> 1][(nt & 1) * 2]);
        }
        int nx = i + NST - 1;
        if (nx < CPS) load_chunk(nx % NST, nx);
        cp_commit();
    }

    // ---- epilogue: partial [ks][oc][n], n-major ----
    const int g = lane >> 2, t0 = lane & 3;
#pragma unroll
    for (int mt = 0; mt < 4; mt++) {
        int oc0 = wm * 64 + mt * 16 + g;
#pragma unroll
        for (int nt = 0; nt < 4; nt++) {
            int n0 = pos0 + wn * 32 + nt * 8 + 2 * t0;
            float* d0 = g_pcp + ((size_t)ks * F2 + oc0) * NTOT + n0;
            *(float2*)d0 = make_float2(acc[mt][nt][0], acc[mt][nt][1]);
            *(float2*)(d0 + (size_t)8 * NTOT) = make_float2(acc[mt][nt][2], acc[mt][nt][3]);
        }
    }
}

// ---------------- fused K-combine + bias + channel gather + squash ---------
__global__ __launch_bounds__(256) void usquash_kernel(const float* __restrict__ bias)
{
    int i = blockIdx.x * 256 + threadIdx.x;
    if (i >= BATCH * PP) return;
    int b = i / PP, p = i - b * PP;
    int mm = p / NPOS, pos = p - mm * NPOS;
    int n = b * NPOS + pos;
    float uu[8]; float sq = 0.f;
#pragma unroll
    for (int e = 0; e < 8; e++) {
        int oc = e * NUM_MAP + mm;
        const float* q = g_pcp + (size_t)oc * NTOT + n;
        float v = bias[oc];
#pragma unroll
        for (int s = 0; s < KSPLIT; s++)
            v += q[(size_t)s * F2 * NTOT];
        uu[e] = v;
        sq += v * v;
    }
    float sc = (sq / (1.f + sq)) * rsqrtf(sq + 1e-8f);
    float4* up = (float4*)(g_u + (size_t)i * 8);
    up[0] = make_float4(uu[0] * sc, uu[1] * sc, uu[2] * sc, uu[3] * sc);
    up[1] = make_float4(uu[4] * sc, uu[5] * sc, uu[6] * sc, uu[7] * sc);
}

// ---------------- routing (1024 thr, shuffle reductions) ----------------
template<bool FIRST>
__global__ __launch_bounds__(1024) void routing_iter(const float* __restrict__ Wd)
{
    const int bc = blockIdx.x;
    const int b = bc / NCLASS, c = bc - b * NCLASS;
    const int tid = threadIdx.x;
    const int lane = tid & 31, wid = tid >> 5;
    __shared__ float swarp[32][10];
    __shared__ float sres[9];
    __shared__ float sM;
    __shared__ float sv16[16];
    __shared__ float sscale;

    const float* bptr = g_bij + (size_t)bc * PP;
    float M = 0.f;
    if (!FIRST) {
        float ml = -1e30f;
        for (int p = tid; p < PP; p += 1024) ml = fmaxf(ml, bptr[p]);
#pragma unroll
        for (int off = 16; off > 0; off >>= 1)
            ml = fmaxf(ml, __shfl_xor_sync(0xffffffffu, ml, off));
        if (lane == 0) swarp[wid][0] = ml;
        __syncthreads();
        if (tid == 0) {
            float mm = swarp[0][0];
            for (int w2 = 1; w2 < 32; w2++) mm = fmaxf(mm, swarp[w2][0]);
            sM = mm;
        }
        __syncthreads();
        M = sM;
    }

    float vals[9];
#pragma unroll
    for (int r = 0; r < 9; r++) vals[r] = 0.f;
    const float4* up = (const float4*)(g_u + (size_t)b * PP * 8);
    for (int p = tid; p < PP; p += 1024) {
        float wgt = FIRST ? 1.f : __expf(bptr[p] - M);
        float4 u0 = up[p * 2], u1 = up[p * 2 + 1];
        vals[0] += wgt;
        vals[1] += wgt * u0.x; vals[2] += wgt * u0.y;
        vals[3] += wgt * u0.z; vals[4] += wgt * u0.w;
        vals[5] += wgt * u1.x; vals[6] += wgt * u1.y;
        vals[7] += wgt * u1.z; vals[8] += wgt * u1.w;
    }
#pragma unroll
    for (int r = 0; r < 9; r++)
#pragma unroll
        for (int off = 16; off > 0; off >>= 1)
            vals[r] += __shfl_xor_sync(0xffffffffu, vals[r], off);
    if (lane == 0)
#pragma unroll
        for (int r = 0; r < 9; r++) swarp[wid][r] = vals[r];
    __syncthreads();
    if (tid < 9) {
        float s = 0.f;
        for (int w2 = 0; w2 < 32; w2++) s += swarp[w2][tid];
        sres[tid] = s;
    }
    __syncthreads();

    const float Zt = sres[0];
    if (tid < DDIM) {
        float s = 0.f;
#pragma unroll
        for (int e = 0; e < 8; e++)
            s += Wd[(c * DDIM + tid) * 8 + e] * (sres[1 + e] / Zt);
        sv16[tid] = s;
    }
    __syncthreads();
    if (tid == 0) {
        float sq = 0.f;
#pragma unroll
        for (int d = 0; d < DDIM; d++) sq += sv16[d] * sv16[d];
        sscale = (sq / (1.f + sq)) * rsqrtf(sq + 1e-8f);
    }
    __syncthreads();
    if (tid < DDIM) {
        float vd = sv16[tid] * sscale;
        g_v[bc * DDIM + tid] = vd;
        sv16[tid] = vd;
    }
    __syncthreads();
    if (tid < CAP_DIM) {
        float w2 = 0.f;
#pragma unroll
        for (int d = 0; d < DDIM; d++)
            w2 += Wd[(c * DDIM + d) * 8 + tid] * sv16[d];
        g_wv[bc * CAP_DIM + tid] = w2;
    }
}

template<bool INIT>
__global__ __launch_bounds__(256) void routing_update()
{
    int i = blockIdx.x * 256 + threadIdx.x;
    if (i >= BATCH * PP) return;
    int b = i / PP, p = i - b * PP;
    const float4* up = (const float4*)(g_u + (size_t)i * 8);
    float4 u0 = up[0], u1 = up[1];
    const float* wvb = g_wv + b * NCLASS * CAP_DIM;
#pragma unroll
    for (int c = 0; c < NCLASS; c++) {
        const float* wv = wvb + c * 8;
        float d = u0.x * wv[0] + u0.y * wv[1] + u0.z * wv[2] + u0.w * wv[3]
                + u1.x * wv[4] + u1.y * wv[5] + u1.z * wv[6] + u1.w * wv[7];
        float* dst = &g_bij[((size_t)(b * NCLASS + c)) * PP + p];
        if (INIT) *dst = d; else *dst += d;
    }
}

// ---------------- finalize ----------------
__global__ void finalize_kernel(float* __restrict__ out)
{
    const int b = blockIdx.x, tid = threadIdx.x;
    __shared__ float svl[NCLASS];
    __shared__ int spred;
    if (tid < NCLASS) {
        float sq = 0.f;
#pragma unroll
        for (int d = 0; d < DDIM; d++) {
            float vv = g_v[(b * NCLASS + tid) * DDIM + d];
            sq += vv * vv;
        }
        svl[tid] = sqrtf(sq);
    }
    __syncthreads();
    if (tid == 0) {
        int pm = 0; float best = svl[0];
        for (int c = 1; c < NCLASS; c++)
            if (svl[c] > best) { best = svl[c]; pm = c; }
        spred = pm;
    }
    __syncthreads();
    if (tid < NCLASS) {
        out[OUT_Y_OFF + b * NCLASS + tid] = (tid == spred) ? 1.0f : 0.0f;
        out[OUT_VL_OFF + b * NCLASS + tid] = svl[tid];
    }
    for (int idx = tid; idx < NCLASS * DDIM; idx += 32) {
        int c = idx >> 4, d = idx & 15;
        g_m[b * NCLASS * DDIM + idx] =
            (c == spred) ? g_v[(b * NCLASS + c) * DDIM + d] : 0.f;
    }
}

// ---------------- decoder ----------------
__global__ __launch_bounds__(256) void dec1_kernel(
    const float* __restrict__ w, const float* __restrict__ bias)
{
    int g = blockIdx.x * 256 + threadIdx.x;
    int b = g >> 9, j = g & 511;
    float acc = bias[j];
#pragma unroll 8
    for (int i = 0; i < 160; i++)
        acc += g_m[b * 160 + i] * w[i * H1N + j];
    g_h1[g] = fmaxf(acc, 0.f);
}

__global__ __launch_bounds__(256) void dec2_kernel(
    const float* __restrict__ w, const float* __restrict__ bias)
{
    int g = blockIdx.x * 256 + threadIdx.x;
    int b = g >> 10, j = g & 1023;
    float acc = bias[j];
#pragma unroll 8
    for (int i = 0; i < H1N; i++)
        acc += g_h1[b * H1N + i] * w[i * H2N + j];
    g_h2[g] = fmaxf(acc, 0.f);
}

__global__ __launch_bounds__(256) void dec3_kernel(
    const float* __restrict__ w, const float* __restrict__ bias,
    float* __restrict__ out)
{
    int jl = threadIdx.x >> 4, b = threadIdx.x & 15;
    int j = blockIdx.x * 16 + jl;
    float acc = bias[j];
#pragma unroll 8
    for (int i = 0; i < H2N; i++)
        acc += g_h2[b * H2N + i] * w[i * RECN + j];
    out[OUT_REC_OFF + b * RECN + j] = 1.f / (1.f + expf(-acc));
}

// ---------------- launch ----------------
extern "C" void kernel_launch(void* const* d_in, const int* in_sizes, int n_in,
                              void* d_out, int out_size)
{
    const float* imgs    = (const float*)d_in[0];
    const float* conv1_w = (const float*)d_in[1];
    const float* conv1_b = (const float*)d_in[2];
    const float* pconv_w = (const float*)d_in[3];
    const float* pconv_b = (const float*)d_in[4];
    const float* W_digit = (const float*)d_in[5];
    const float* dec_w1  = (const float*)d_in[6];
    const float* dec_b1  = (const float*)d_in[7];
    const float* dec_w2  = (const float*)d_in[8];
    const float* dec_b2  = (const float*)d_in[9];
    const float* dec_w3  = (const float*)d_in[10];
    const float* dec_b3  = (const float*)d_in[11];
    float* out = (float*)d_out;

    const int smem_bytes = NST * STG;   // 102400
    cudaFuncSetAttribute(pconv_mma_kernel,
                         cudaFuncAttributeMaxDynamicSharedMemorySize, smem_bytes);

    conv1_kernel<<<dim3(4, CONV1_H, BATCH), 256>>>(imgs, conv1_w, conv1_b);
    wprep_kernel<<<(F2 * KTOT + 255) / 256, 256>>>(pconv_w);
    pconv_mma_kernel<<<dim3(NTOT / 64, KSPLIT), 256, smem_bytes>>>();
    usquash_kernel<<<(BATCH * PP) / 256, 256>>>(pconv_b);

    routing_iter<true><<<BATCH * NCLASS, 1024>>>(W_digit);
    routing_update<true><<<(BATCH * PP) / 256, 256>>>();
    routing_iter<false><<<BATCH * NCLASS, 1024>>>(W_digit);
    routing_update<false><<<(BATCH * PP) / 256, 256>>>();
    routing_iter<false><<<BATCH * NCLASS, 1024>>>(W_digit);

    finalize_kernel<<<BATCH, 32>>>(out);
    dec1_kernel<<<(BATCH * H1N) / 256, 256>>>(dec_w1, dec_b1);
    dec2_kernel<<<(BATCH * H2N) / 256, 256>>>(dec_w2, dec_b2);
    dec3_kernel<<<RECN / 16, 256>>>(dec_w3, dec_b3, out);
}